// round 1
// baseline (speedup 1.0000x reference)
#include <cuda_runtime.h>
#include <cuda_bf16.h>
#include <math.h>

// Problem constants (fixed by the dataset)
#define H_DIM 128
#define R_DIM 6
#define D_DIM 256
#define L_LAYERS 3
#define MAX_NODES 50000

// Scratch (static device globals are the sanctioned scratch mechanism)
__device__ float g_agg[(size_t)MAX_NODES * H_DIM];   // 25.6 MB
__device__ float g_y0 [(size_t)MAX_NODES * D_DIM];   // 51.2 MB
__device__ float g_y1 [(size_t)MAX_NODES * D_DIM];   // 51.2 MB

// ---------------------------------------------------------------------------
// Zero the aggregation buffer
// ---------------------------------------------------------------------------
__global__ void zero_kernel(float4* __restrict__ p, int n4) {
    int i = blockIdx.x * blockDim.x + threadIdx.x;
    int stride = gridDim.x * blockDim.x;
    float4 z = make_float4(0.f, 0.f, 0.f, 0.f);
    for (; i < n4; i += stride) p[i] = z;
}

// ---------------------------------------------------------------------------
// Edge stage: agg[i[e], h] += (sum_r rbf[e,r] * W_rbf[h,r]) * x[e,h]
// One warp per edge (grid-stride). Lane handles 4 consecutive channels.
// W_rbf rows hoisted into registers (fixed per lane across edges).
// Scatter via vectorized red.global.add.v4.f32 (16B, no return).
// ---------------------------------------------------------------------------
__global__ void edge_kernel(const float* __restrict__ x,
                            const float* __restrict__ rbf,
                            const int*   __restrict__ idx,
                            const float* __restrict__ Wrbf,
                            float*       __restrict__ agg,
                            int E) {
    const int lane = threadIdx.x & 31;
    const int warp = (blockIdx.x * blockDim.x + threadIdx.x) >> 5;
    const int nwarps = (gridDim.x * blockDim.x) >> 5;

    // Hoist this lane's 4 channel weight rows (4 x 6) into registers.
    float w[4][6];
    #pragma unroll
    for (int j = 0; j < 4; ++j)
        #pragma unroll
        for (int r = 0; r < R_DIM; ++r)
            w[j][r] = __ldg(Wrbf + (lane * 4 + j) * R_DIM + r);

    for (int e = warp; e < E; e += nwarps) {
        // rbf row: 6 floats = 3x float2 broadcast loads (24B-aligned rows)
        const float2* rp = reinterpret_cast<const float2*>(rbf + (size_t)e * R_DIM);
        float2 r01 = __ldg(rp + 0);
        float2 r23 = __ldg(rp + 1);
        float2 r45 = __ldg(rp + 2);
        int node = __ldg(idx + e);
        float4 xv = __ldg(reinterpret_cast<const float4*>(x + (size_t)e * H_DIM) + lane);

        float g0 = w[0][0]*r01.x + w[0][1]*r01.y + w[0][2]*r23.x
                 + w[0][3]*r23.y + w[0][4]*r45.x + w[0][5]*r45.y;
        float g1 = w[1][0]*r01.x + w[1][1]*r01.y + w[1][2]*r23.x
                 + w[1][3]*r23.y + w[1][4]*r45.x + w[1][5]*r45.y;
        float g2 = w[2][0]*r01.x + w[2][1]*r01.y + w[2][2]*r23.x
                 + w[2][3]*r23.y + w[2][4]*r45.x + w[2][5]*r45.y;
        float g3 = w[3][0]*r01.x + w[3][1]*r01.y + w[3][2]*r23.x
                 + w[3][3]*r23.y + w[3][4]*r45.x + w[3][5]*r45.y;

        float vx = g0 * xv.x, vy = g1 * xv.y, vz = g2 * xv.z, vw = g3 * xv.w;
        float* dst = agg + (size_t)node * H_DIM + lane * 4;
        asm volatile("red.global.add.v4.f32 [%0], {%1, %2, %3, %4};"
                     :: "l"(dst), "f"(vx), "f"(vy), "f"(vz), "f"(vw)
                     : "memory");
    }
}

// ---------------------------------------------------------------------------
// Tiled SGEMM: C[M,N] = act(A[M,K] @ B[N,K]^T + bias)
// BM=128, BN=128, BK=8, 256 threads, 8x8 per thread.
// B is a torch-Linear weight: [out_features, in_features] row-major.
// ---------------------------------------------------------------------------
template <bool BIAS, bool SILU>
__global__ void __launch_bounds__(256)
gemm_bt(const float* __restrict__ A, const float* __restrict__ B,
        const float* __restrict__ bias, float* __restrict__ C,
        int M, int N, int K) {
    __shared__ float As[8 * 128];   // transposed: As[k][m]
    __shared__ float Bs[8 * 128];   // transposed: Bs[k][n]

    const int t   = threadIdx.x;
    const int m0  = blockIdx.y * 128;
    const int n0  = blockIdx.x * 128;
    const int row = t >> 1;            // 0..127
    const int col4 = (t & 1) * 4;      // 0 or 4
    const int tx = t & 15;             // n-frag
    const int ty = t >> 4;             // m-frag

    float acc[8][8];
    #pragma unroll
    for (int i = 0; i < 8; ++i)
        #pragma unroll
        for (int j = 0; j < 8; ++j) acc[i][j] = 0.f;

    for (int k0 = 0; k0 < K; k0 += 8) {
        float4 av = make_float4(0.f, 0.f, 0.f, 0.f);
        if (m0 + row < M)
            av = *reinterpret_cast<const float4*>(A + (size_t)(m0 + row) * K + k0 + col4);
        float4 bv = *reinterpret_cast<const float4*>(B + (size_t)(n0 + row) * K + k0 + col4);

        As[(col4 + 0) * 128 + row] = av.x;
        As[(col4 + 1) * 128 + row] = av.y;
        As[(col4 + 2) * 128 + row] = av.z;
        As[(col4 + 3) * 128 + row] = av.w;
        Bs[(col4 + 0) * 128 + row] = bv.x;
        Bs[(col4 + 1) * 128 + row] = bv.y;
        Bs[(col4 + 2) * 128 + row] = bv.z;
        Bs[(col4 + 3) * 128 + row] = bv.w;
        __syncthreads();

        #pragma unroll
        for (int k = 0; k < 8; ++k) {
            float ra[8], rb[8];
            *reinterpret_cast<float4*>(ra)     = *reinterpret_cast<const float4*>(As + k * 128 + ty * 8);
            *reinterpret_cast<float4*>(ra + 4) = *reinterpret_cast<const float4*>(As + k * 128 + ty * 8 + 4);
            *reinterpret_cast<float4*>(rb)     = *reinterpret_cast<const float4*>(Bs + k * 128 + tx * 8);
            *reinterpret_cast<float4*>(rb + 4) = *reinterpret_cast<const float4*>(Bs + k * 128 + tx * 8 + 4);
            #pragma unroll
            for (int i = 0; i < 8; ++i)
                #pragma unroll
                for (int j = 0; j < 8; ++j)
                    acc[i][j] = fmaf(ra[i], rb[j], acc[i][j]);
        }
        __syncthreads();
    }

    // Epilogue
    #pragma unroll
    for (int i = 0; i < 8; ++i) {
        int m = m0 + ty * 8 + i;
        if (m >= M) continue;
        float out[8];
        #pragma unroll
        for (int j = 0; j < 8; ++j) {
            float v = acc[i][j];
            if (BIAS) v += __ldg(bias + n0 + tx * 8 + j);
            if (SILU) v = v / (1.f + __expf(-v));
            out[j] = v;
        }
        float* cp = C + (size_t)m * N + n0 + tx * 8;
        *reinterpret_cast<float4*>(cp)     = *reinterpret_cast<const float4*>(out);
        *reinterpret_cast<float4*>(cp + 4) = *reinterpret_cast<const float4*>(out + 4);
    }
}

// ---------------------------------------------------------------------------
// Final projection: out[m] = Y[m,:] . W_out[0,:]   (C == 1, D == 256)
// One warp per node.
// ---------------------------------------------------------------------------
__global__ void final_dot(const float* __restrict__ Y,
                          const float* __restrict__ Wout,
                          float* __restrict__ out, int M) {
    int warp = (blockIdx.x * blockDim.x + threadIdx.x) >> 5;
    int lane = threadIdx.x & 31;
    if (warp >= M) return;
    const float4* yp = reinterpret_cast<const float4*>(Y + (size_t)warp * D_DIM);
    const float4* wp = reinterpret_cast<const float4*>(Wout);
    float s = 0.f;
    #pragma unroll
    for (int c = 0; c < 2; ++c) {
        float4 yv = __ldg(yp + lane + 32 * c);
        float4 wv = __ldg(wp + lane + 32 * c);
        s += yv.x * wv.x + yv.y * wv.y + yv.z * wv.z + yv.w * wv.w;
    }
    #pragma unroll
    for (int off = 16; off; off >>= 1)
        s += __shfl_down_sync(0xffffffffu, s, off);
    if (lane == 0) out[warp] = s;
}

// ---------------------------------------------------------------------------
// Launch
// Inputs: 0:x[E,128] 1:rbf[E,6] 2:i[E] 3:W_rbf[128,6] 4:W_up[256,128]
//         5:Ws[3,256,256] 6:bs[3,256] 7:W_out[1,256] (8:num_nodes)
// ---------------------------------------------------------------------------
extern "C" void kernel_launch(void* const* d_in, const int* in_sizes, int n_in,
                              void* d_out, int out_size) {
    const float* x     = (const float*)d_in[0];
    const float* rbf   = (const float*)d_in[1];
    const int*   idx   = (const int*)  d_in[2];
    const float* W_rbf = (const float*)d_in[3];
    const float* W_up  = (const float*)d_in[4];
    const float* Ws    = (const float*)d_in[5];
    const float* bs    = (const float*)d_in[6];
    const float* W_out = (const float*)d_in[7];
    float* out = (float*)d_out;

    const int E = in_sizes[2];        // one int per edge
    const int M = out_size;           // C == 1 -> out_size == num_nodes

    float *agg, *y0, *y1;
    cudaGetSymbolAddress((void**)&agg, g_agg);
    cudaGetSymbolAddress((void**)&y0,  g_y0);
    cudaGetSymbolAddress((void**)&y1,  g_y1);

    // 1) zero agg
    {
        int n4 = M * H_DIM / 4;
        zero_kernel<<<1024, 256>>>((float4*)agg, n4);
    }
    // 2) edge scatter
    edge_kernel<<<1184, 256>>>(x, rbf, idx, W_rbf, agg, E);

    // 3) up-projection: y0 = agg @ W_up^T   [M,256], K=128
    {
        dim3 grid(D_DIM / 128, (M + 127) / 128);
        gemm_bt<false, false><<<grid, 256>>>(agg, W_up, nullptr, y0, M, D_DIM, H_DIM);
    }
    // 4) 3x silu(y @ W^T + b), ping-pong y0 <-> y1
    {
        dim3 grid(D_DIM / 128, (M + 127) / 128);
        gemm_bt<true, true><<<grid, 256>>>(y0, Ws + 0 * D_DIM * D_DIM, bs + 0 * D_DIM, y1, M, D_DIM, D_DIM);
        gemm_bt<true, true><<<grid, 256>>>(y1, Ws + 1 * D_DIM * D_DIM, bs + 1 * D_DIM, y0, M, D_DIM, D_DIM);
        gemm_bt<true, true><<<grid, 256>>>(y0, Ws + 2 * D_DIM * D_DIM, bs + 2 * D_DIM, y1, M, D_DIM, D_DIM);
    }
    // 5) final projection
    {
        int warps_per_block = 8;
        int blocks = (M + warps_per_block - 1) / warps_per_block;
        final_dot<<<blocks, warps_per_block * 32>>>(y1, W_out, out, M);
    }
}

// round 2
// speedup vs baseline: 1.0142x; 1.0142x over previous
#include <cuda_runtime.h>
#include <cuda_bf16.h>
#include <math.h>

// Problem constants (fixed by the dataset)
#define H_DIM 128
#define R_DIM 6
#define D_DIM 256
#define L_LAYERS 3
#define MAX_NODES 50000

// Scratch
__device__ float g_agg[(size_t)MAX_NODES * H_DIM];   // 25.6 MB
__device__ float g_y0 [(size_t)MAX_NODES * D_DIM];   // 51.2 MB
__device__ float g_y1 [(size_t)MAX_NODES * D_DIM];   // 51.2 MB

typedef unsigned long long ull;

__device__ __forceinline__ ull pack2(float lo, float hi) {
    ull r;
    asm("mov.b64 %0, {%1, %2};" : "=l"(r) : "f"(lo), "f"(hi));
    return r;
}
__device__ __forceinline__ void unpack2(ull v, float& lo, float& hi) {
    asm("mov.b64 {%0, %1}, %2;" : "=f"(lo), "=f"(hi) : "l"(v));
}
// d += a * b  (packed 2x fp32, SASS FFMA2)
__device__ __forceinline__ void ffma2(ull& d, ull a, ull b) {
    asm("fma.rn.f32x2 %0, %1, %2, %0;" : "+l"(d) : "l"(a), "l"(b));
}

// ---------------------------------------------------------------------------
// Zero the aggregation buffer
// ---------------------------------------------------------------------------
__global__ void zero_kernel(float4* __restrict__ p, int n4) {
    int i = blockIdx.x * blockDim.x + threadIdx.x;
    int stride = gridDim.x * blockDim.x;
    float4 z = make_float4(0.f, 0.f, 0.f, 0.f);
    for (; i < n4; i += stride) p[i] = z;
}

// ---------------------------------------------------------------------------
// Edge stage: agg[i[e], h] += (sum_r rbf[e,r] * W_rbf[h,r]) * x[e,h]
// One warp per edge (grid-stride). Lane handles 4 consecutive channels.
// ---------------------------------------------------------------------------
__global__ void edge_kernel(const float* __restrict__ x,
                            const float* __restrict__ rbf,
                            const int*   __restrict__ idx,
                            const float* __restrict__ Wrbf,
                            float*       __restrict__ agg,
                            int E) {
    const int lane = threadIdx.x & 31;
    const int warp = (blockIdx.x * blockDim.x + threadIdx.x) >> 5;
    const int nwarps = (gridDim.x * blockDim.x) >> 5;

    float w[4][6];
    #pragma unroll
    for (int j = 0; j < 4; ++j)
        #pragma unroll
        for (int r = 0; r < R_DIM; ++r)
            w[j][r] = __ldg(Wrbf + (lane * 4 + j) * R_DIM + r);

    for (int e = warp; e < E; e += nwarps) {
        const float2* rp = reinterpret_cast<const float2*>(rbf + (size_t)e * R_DIM);
        float2 r01 = __ldg(rp + 0);
        float2 r23 = __ldg(rp + 1);
        float2 r45 = __ldg(rp + 2);
        int node = __ldg(idx + e);
        float4 xv = __ldg(reinterpret_cast<const float4*>(x + (size_t)e * H_DIM) + lane);

        float g0 = w[0][0]*r01.x + w[0][1]*r01.y + w[0][2]*r23.x
                 + w[0][3]*r23.y + w[0][4]*r45.x + w[0][5]*r45.y;
        float g1 = w[1][0]*r01.x + w[1][1]*r01.y + w[1][2]*r23.x
                 + w[1][3]*r23.y + w[1][4]*r45.x + w[1][5]*r45.y;
        float g2 = w[2][0]*r01.x + w[2][1]*r01.y + w[2][2]*r23.x
                 + w[2][3]*r23.y + w[2][4]*r45.x + w[2][5]*r45.y;
        float g3 = w[3][0]*r01.x + w[3][1]*r01.y + w[3][2]*r23.x
                 + w[3][3]*r23.y + w[3][4]*r45.x + w[3][5]*r45.y;

        float vx = g0 * xv.x, vy = g1 * xv.y, vz = g2 * xv.z, vw = g3 * xv.w;
        float* dst = agg + (size_t)node * H_DIM + lane * 4;
        asm volatile("red.global.add.v4.f32 [%0], {%1, %2, %3, %4};"
                     :: "l"(dst), "f"(vx), "f"(vy), "f"(vz), "f"(vw)
                     : "memory");
    }
}

// ---------------------------------------------------------------------------
// Tiled SGEMM with packed f32x2 FFMA2 inner product.
// C[M,N] = act(A[M,K] @ B[N,K]^T + bias)
// BM=128, BN=128, BK=8, 256 threads, 8x8 outputs per thread (as 8x4 f32x2).
// ---------------------------------------------------------------------------
template <bool BIAS, bool SILU>
__global__ void __launch_bounds__(256)
gemm_bt(const float* __restrict__ A, const float* __restrict__ B,
        const float* __restrict__ bias, float* __restrict__ C,
        int M, int N, int K) {
    __shared__ float As[8 * 128];   // As[k][m]
    __shared__ float Bs[8 * 128];   // Bs[k][n]

    const int t   = threadIdx.x;
    const int m0  = blockIdx.y * 128;
    const int n0  = blockIdx.x * 128;
    const int row = t >> 1;
    const int col4 = (t & 1) * 4;
    const int tx = t & 15;             // n-frag
    const int ty = t >> 4;             // m-frag

    ull accp[8][4];
    #pragma unroll
    for (int i = 0; i < 8; ++i)
        #pragma unroll
        for (int j = 0; j < 4; ++j) accp[i][j] = 0ull;

    for (int k0 = 0; k0 < K; k0 += 8) {
        float4 av = make_float4(0.f, 0.f, 0.f, 0.f);
        if (m0 + row < M)
            av = *reinterpret_cast<const float4*>(A + (size_t)(m0 + row) * K + k0 + col4);
        float4 bv = *reinterpret_cast<const float4*>(B + (size_t)(n0 + row) * K + k0 + col4);

        As[(col4 + 0) * 128 + row] = av.x;
        As[(col4 + 1) * 128 + row] = av.y;
        As[(col4 + 2) * 128 + row] = av.z;
        As[(col4 + 3) * 128 + row] = av.w;
        Bs[(col4 + 0) * 128 + row] = bv.x;
        Bs[(col4 + 1) * 128 + row] = bv.y;
        Bs[(col4 + 2) * 128 + row] = bv.z;
        Bs[(col4 + 3) * 128 + row] = bv.w;
        __syncthreads();

        #pragma unroll
        for (int k = 0; k < 8; ++k) {
            float ra[8], rb[8];
            *reinterpret_cast<float4*>(ra)     = *reinterpret_cast<const float4*>(As + k * 128 + ty * 8);
            *reinterpret_cast<float4*>(ra + 4) = *reinterpret_cast<const float4*>(As + k * 128 + ty * 8 + 4);
            *reinterpret_cast<float4*>(rb)     = *reinterpret_cast<const float4*>(Bs + k * 128 + tx * 8);
            *reinterpret_cast<float4*>(rb + 4) = *reinterpret_cast<const float4*>(Bs + k * 128 + tx * 8 + 4);

            ull rbp[4];
            #pragma unroll
            for (int j = 0; j < 4; ++j) rbp[j] = pack2(rb[2 * j], rb[2 * j + 1]);
            #pragma unroll
            for (int i = 0; i < 8; ++i) {
                ull rap = pack2(ra[i], ra[i]);
                #pragma unroll
                for (int j = 0; j < 4; ++j)
                    ffma2(accp[i][j], rap, rbp[j]);
            }
        }
        __syncthreads();
    }

    // Epilogue
    #pragma unroll
    for (int i = 0; i < 8; ++i) {
        int m = m0 + ty * 8 + i;
        if (m >= M) continue;
        float out[8];
        #pragma unroll
        for (int j = 0; j < 4; ++j)
            unpack2(accp[i][j], out[2 * j], out[2 * j + 1]);
        #pragma unroll
        for (int j = 0; j < 8; ++j) {
            float v = out[j];
            if (BIAS) v += __ldg(bias + n0 + tx * 8 + j);
            if (SILU) v = v / (1.f + __expf(-v));
            out[j] = v;
        }
        float* cp = C + (size_t)m * N + n0 + tx * 8;
        *reinterpret_cast<float4*>(cp)     = *reinterpret_cast<const float4*>(out);
        *reinterpret_cast<float4*>(cp + 4) = *reinterpret_cast<const float4*>(out + 4);
    }
}

// ---------------------------------------------------------------------------
// Final projection: out[m] = Y[m,:] . W_out[0,:]   (C == 1, D == 256)
// ---------------------------------------------------------------------------
__global__ void final_dot(const float* __restrict__ Y,
                          const float* __restrict__ Wout,
                          float* __restrict__ out, int M) {
    int warp = (blockIdx.x * blockDim.x + threadIdx.x) >> 5;
    int lane = threadIdx.x & 31;
    if (warp >= M) return;
    const float4* yp = reinterpret_cast<const float4*>(Y + (size_t)warp * D_DIM);
    const float4* wp = reinterpret_cast<const float4*>(Wout);
    float s = 0.f;
    #pragma unroll
    for (int c = 0; c < 2; ++c) {
        float4 yv = __ldg(yp + lane + 32 * c);
        float4 wv = __ldg(wp + lane + 32 * c);
        s += yv.x * wv.x + yv.y * wv.y + yv.z * wv.z + yv.w * wv.w;
    }
    #pragma unroll
    for (int off = 16; off; off >>= 1)
        s += __shfl_down_sync(0xffffffffu, s, off);
    if (lane == 0) out[warp] = s;
}

// ---------------------------------------------------------------------------
// Launch
// Inputs: 0:x[E,128] 1:rbf[E,6] 2:i[E] 3:W_rbf[128,6] 4:W_up[256,128]
//         5:Ws[3,256,256] 6:bs[3,256] 7:W_out[1,256] (8:num_nodes)
// ---------------------------------------------------------------------------
extern "C" void kernel_launch(void* const* d_in, const int* in_sizes, int n_in,
                              void* d_out, int out_size) {
    const float* x     = (const float*)d_in[0];
    const float* rbf   = (const float*)d_in[1];
    const int*   idx   = (const int*)  d_in[2];
    const float* W_rbf = (const float*)d_in[3];
    const float* W_up  = (const float*)d_in[4];
    const float* Ws    = (const float*)d_in[5];
    const float* bs    = (const float*)d_in[6];
    const float* W_out = (const float*)d_in[7];
    float* out = (float*)d_out;

    const int E = in_sizes[2];
    const int M = out_size;           // C == 1 -> out_size == num_nodes

    float *agg, *y0, *y1;
    cudaGetSymbolAddress((void**)&agg, g_agg);
    cudaGetSymbolAddress((void**)&y0,  g_y0);
    cudaGetSymbolAddress((void**)&y1,  g_y1);

    // 1) zero agg
    {
        int n4 = M * H_DIM / 4;
        zero_kernel<<<1024, 256>>>((float4*)agg, n4);
    }
    // 2) edge scatter
    edge_kernel<<<1184, 256>>>(x, rbf, idx, W_rbf, agg, E);

    // 3) up-projection: y0 = agg @ W_up^T   [M,256], K=128
    {
        dim3 grid(D_DIM / 128, (M + 127) / 128);
        gemm_bt<false, false><<<grid, 256>>>(agg, W_up, nullptr, y0, M, D_DIM, H_DIM);
    }
    // 4) 3x silu(y @ W^T + b), ping-pong y0 <-> y1
    {
        dim3 grid(D_DIM / 128, (M + 127) / 128);
        gemm_bt<true, true><<<grid, 256>>>(y0, Ws + 0 * D_DIM * D_DIM, bs + 0 * D_DIM, y1, M, D_DIM, D_DIM);
        gemm_bt<true, true><<<grid, 256>>>(y1, Ws + 1 * D_DIM * D_DIM, bs + 1 * D_DIM, y0, M, D_DIM, D_DIM);
        gemm_bt<true, true><<<grid, 256>>>(y0, Ws + 2 * D_DIM * D_DIM, bs + 2 * D_DIM, y1, M, D_DIM, D_DIM);
    }
    // 5) final projection
    {
        int warps_per_block = 8;
        int blocks = (M + warps_per_block - 1) / warps_per_block;
        final_dot<<<blocks, warps_per_block * 32>>>(y1, W_out, out, M);
    }
}

// round 4
// speedup vs baseline: 1.6236x; 1.6009x over previous
#include <cuda_runtime.h>
#include <cuda_bf16.h>
#include <cstdint>
#include <math.h>

#define H_DIM 128
#define R_DIM 6
#define D_DIM 256
#define MAX_NODES 50000

// Scratch
__device__ float g_agg[(size_t)MAX_NODES * H_DIM];
__device__ float g_y0 [(size_t)MAX_NODES * D_DIM];
__device__ float g_y1 [(size_t)MAX_NODES * D_DIM];
// Pre-split weights (bf16 hi/lo): [0,32768) = W_up (256x128), then 3x Ws (256x256)
#define W_TOTAL (256*128 + 3*256*256)
__device__ __nv_bfloat16 g_whi[W_TOTAL];
__device__ __nv_bfloat16 g_wlo[W_TOTAL];

__device__ __forceinline__ uint32_t pack_bf16(float a, float b) {
    __nv_bfloat162 v(__float2bfloat16_rn(a), __float2bfloat16_rn(b));
    return *reinterpret_cast<uint32_t*>(&v);
}

// ---------------------------------------------------------------------------
// Weight prep: split fp32 weights into bf16 hi/lo
// ---------------------------------------------------------------------------
__global__ void prep_w(const float* __restrict__ W_up, const float* __restrict__ Ws,
                       __nv_bfloat16* __restrict__ whi, __nv_bfloat16* __restrict__ wlo) {
    int i = blockIdx.x * blockDim.x + threadIdx.x;
    int stride = gridDim.x * blockDim.x;
    for (; i < W_TOTAL; i += stride) {
        float v = (i < 256 * 128) ? W_up[i] : Ws[i - 256 * 128];
        __nv_bfloat16 h = __float2bfloat16_rn(v);
        float lo = v - __bfloat162float(h);
        whi[i] = h;
        wlo[i] = __float2bfloat16_rn(lo);
    }
}

__global__ void zero_kernel(float4* __restrict__ p, int n4) {
    int i = blockIdx.x * blockDim.x + threadIdx.x;
    int stride = gridDim.x * blockDim.x;
    float4 z = make_float4(0.f, 0.f, 0.f, 0.f);
    for (; i < n4; i += stride) p[i] = z;
}

// ---------------------------------------------------------------------------
// Edge stage (unchanged)
// ---------------------------------------------------------------------------
__global__ void edge_kernel(const float* __restrict__ x,
                            const float* __restrict__ rbf,
                            const int*   __restrict__ idx,
                            const float* __restrict__ Wrbf,
                            float*       __restrict__ agg,
                            int E) {
    const int lane = threadIdx.x & 31;
    const int warp = (blockIdx.x * blockDim.x + threadIdx.x) >> 5;
    const int nwarps = (gridDim.x * blockDim.x) >> 5;

    float w[4][6];
    #pragma unroll
    for (int j = 0; j < 4; ++j)
        #pragma unroll
        for (int r = 0; r < R_DIM; ++r)
            w[j][r] = __ldg(Wrbf + (lane * 4 + j) * R_DIM + r);

    for (int e = warp; e < E; e += nwarps) {
        const float2* rp = reinterpret_cast<const float2*>(rbf + (size_t)e * R_DIM);
        float2 r01 = __ldg(rp + 0);
        float2 r23 = __ldg(rp + 1);
        float2 r45 = __ldg(rp + 2);
        int node = __ldg(idx + e);
        float4 xv = __ldg(reinterpret_cast<const float4*>(x + (size_t)e * H_DIM) + lane);

        float g0 = w[0][0]*r01.x + w[0][1]*r01.y + w[0][2]*r23.x + w[0][3]*r23.y + w[0][4]*r45.x + w[0][5]*r45.y;
        float g1 = w[1][0]*r01.x + w[1][1]*r01.y + w[1][2]*r23.x + w[1][3]*r23.y + w[1][4]*r45.x + w[1][5]*r45.y;
        float g2 = w[2][0]*r01.x + w[2][1]*r01.y + w[2][2]*r23.x + w[2][3]*r23.y + w[2][4]*r45.x + w[2][5]*r45.y;
        float g3 = w[3][0]*r01.x + w[3][1]*r01.y + w[3][2]*r23.x + w[3][3]*r23.y + w[3][4]*r45.x + w[3][5]*r45.y;

        float vx = g0 * xv.x, vy = g1 * xv.y, vz = g2 * xv.z, vw = g3 * xv.w;
        float* dst = agg + (size_t)node * H_DIM + lane * 4;
        asm volatile("red.global.add.v4.f32 [%0], {%1, %2, %3, %4};"
                     :: "l"(dst), "f"(vx), "f"(vy), "f"(vz), "f"(vw) : "memory");
    }
}

// ---------------------------------------------------------------------------
// bf16 mma.sync GEMM with 2-term split: Y = act(A @ B^T + bias)
// CTA tile 128(m) x 128(n), 8 warps of 32x64. K chunks of 32.
// SMEM: A_hi/A_lo/B_hi/B_lo, each 128 rows x 40 halfwords (8 pad) = 10 KB.
// PROJ fuses out[m] += sum_c act(...)*wout[c] via red.global.add.
// ---------------------------------------------------------------------------
#define STRIDE_H 40   // halfwords per SMEM row (32 data + 8 pad) -> conflict-free

__device__ __forceinline__ void mma_bf16(float* d, const uint32_t* a, uint32_t b0, uint32_t b1) {
    asm("mma.sync.aligned.m16n8k16.row.col.f32.bf16.bf16.f32 "
        "{%0,%1,%2,%3}, {%4,%5,%6,%7}, {%8,%9}, {%0,%1,%2,%3};"
        : "+f"(d[0]), "+f"(d[1]), "+f"(d[2]), "+f"(d[3])
        : "r"(a[0]), "r"(a[1]), "r"(a[2]), "r"(a[3]), "r"(b0), "r"(b1));
}

template<int K_TOTAL, bool BIAS, bool SILU, bool PROJ>
__global__ void __launch_bounds__(256, 2)
gemm_mma(const float* __restrict__ A,
         const __nv_bfloat16* __restrict__ Bhi,
         const __nv_bfloat16* __restrict__ Blo,
         const float* __restrict__ bias,
         const float* __restrict__ wout,
         float* __restrict__ Y,
         int M) {
    __shared__ __align__(16) uint16_t sAhi[128 * STRIDE_H];
    __shared__ __align__(16) uint16_t sAlo[128 * STRIDE_H];
    __shared__ __align__(16) uint16_t sBhi[128 * STRIDE_H];
    __shared__ __align__(16) uint16_t sBlo[128 * STRIDE_H];

    const int tid  = threadIdx.x;
    const int wid  = tid >> 5, lane = tid & 31;
    const int g    = lane >> 2, t = lane & 3;
    const int m0   = blockIdx.x * 128;
    const int n0   = blockIdx.y * 128;        // global col base of this CTA
    const int wm   = (wid & 3) * 32;          // warp m offset in tile
    const int wn   = (wid >> 2) * 64;         // warp n offset in tile

    float acc[2][8][4];
    #pragma unroll
    for (int i = 0; i < 2; ++i)
        #pragma unroll
        for (int j = 0; j < 8; ++j)
            #pragma unroll
            for (int q = 0; q < 4; ++q) acc[i][j][q] = 0.f;

    const uint32_t* A32hi = reinterpret_cast<const uint32_t*>(sAhi);
    const uint32_t* A32lo = reinterpret_cast<const uint32_t*>(sAlo);
    const uint32_t* B32hi = reinterpret_cast<const uint32_t*>(sBhi);
    const uint32_t* B32lo = reinterpret_cast<const uint32_t*>(sBlo);

    const int fr = tid >> 1;        // fill row (0..127)
    const int fh = tid & 1;         // fill half (k 0..15 or 16..31)
    const bool a_valid = (m0 + fr) < M;

    for (int c = 0; c < K_TOTAL / 32; ++c) {
        // ---- fill A (fp32 -> bf16 hi/lo) ----
        {
            const float* ap = A + (size_t)(m0 + fr) * K_TOTAL + c * 32 + fh * 16;
            #pragma unroll
            for (int q4 = 0; q4 < 2; ++q4) {
                float4 f0 = make_float4(0.f,0.f,0.f,0.f), f1 = f0;
                if (a_valid) {
                    f0 = *reinterpret_cast<const float4*>(ap + q4 * 8);
                    f1 = *reinterpret_cast<const float4*>(ap + q4 * 8 + 4);
                }
                uint4 Hv, Lv;
                Hv.x = pack_bf16(f0.x, f0.y); Hv.y = pack_bf16(f0.z, f0.w);
                Hv.z = pack_bf16(f1.x, f1.y); Hv.w = pack_bf16(f1.z, f1.w);
                float e0 = f0.x - __bfloat162float(__float2bfloat16_rn(f0.x));
                float e1 = f0.y - __bfloat162float(__float2bfloat16_rn(f0.y));
                float e2 = f0.z - __bfloat162float(__float2bfloat16_rn(f0.z));
                float e3 = f0.w - __bfloat162float(__float2bfloat16_rn(f0.w));
                float e4 = f1.x - __bfloat162float(__float2bfloat16_rn(f1.x));
                float e5 = f1.y - __bfloat162float(__float2bfloat16_rn(f1.y));
                float e6 = f1.z - __bfloat162float(__float2bfloat16_rn(f1.z));
                float e7 = f1.w - __bfloat162float(__float2bfloat16_rn(f1.w));
                Lv.x = pack_bf16(e0, e1); Lv.y = pack_bf16(e2, e3);
                Lv.z = pack_bf16(e4, e5); Lv.w = pack_bf16(e6, e7);
                int hw = fr * STRIDE_H + fh * 16 + q4 * 8;     // halfword index, 16B aligned
                *reinterpret_cast<uint4*>(sAhi + hw) = Hv;
                *reinterpret_cast<uint4*>(sAlo + hw) = Lv;
            }
        }
        // ---- fill B (bf16 copy) ----
        {
            const size_t boff = (size_t)(n0 + fr) * K_TOTAL + c * 32 + fh * 16;
            const uint4* bh = reinterpret_cast<const uint4*>(Bhi + boff);
            const uint4* bl = reinterpret_cast<const uint4*>(Blo + boff);
            int hw = fr * STRIDE_H + fh * 16;
            *reinterpret_cast<uint4*>(sBhi + hw)     = bh[0];
            *reinterpret_cast<uint4*>(sBhi + hw + 8) = bh[1];
            *reinterpret_cast<uint4*>(sBlo + hw)     = bl[0];
            *reinterpret_cast<uint4*>(sBlo + hw + 8) = bl[1];
        }
        __syncthreads();

        // ---- compute: 2 ksteps x (3 products) ----
        #pragma unroll
        for (int ks = 0; ks < 2; ++ks) {
            const int kw = ks * 8;   // k offset in 32-bit words
            uint32_t ahi[2][4], alo[2][4];
            #pragma unroll
            for (int i = 0; i < 2; ++i) {
                int r0 = (wm + i * 16 + g) * (STRIDE_H / 2) + kw + t;  // STRIDE_H/2=20 words
                ahi[i][0] = A32hi[r0];        ahi[i][1] = A32hi[r0 + 160];
                ahi[i][2] = A32hi[r0 + 4];    ahi[i][3] = A32hi[r0 + 164];
                alo[i][0] = A32lo[r0];        alo[i][1] = A32lo[r0 + 160];
                alo[i][2] = A32lo[r0 + 4];    alo[i][3] = A32lo[r0 + 164];
            }
            #pragma unroll
            for (int j = 0; j < 8; ++j) {
                int nb = (wn + j * 8 + g) * (STRIDE_H / 2) + kw + t;
                uint32_t bh0 = B32hi[nb], bh1 = B32hi[nb + 4];
                uint32_t bl0 = B32lo[nb], bl1 = B32lo[nb + 4];
                #pragma unroll
                for (int i = 0; i < 2; ++i) {
                    mma_bf16(acc[i][j], ahi[i], bh0, bh1);
                    mma_bf16(acc[i][j], ahi[i], bl0, bl1);
                    mma_bf16(acc[i][j], alo[i], bh0, bh1);
                }
            }
        }
        __syncthreads();
    }

    // ---- epilogue ----
    // Thread owns: rows m0+wm+i*16+g (+8), cols n0+wn+j*8+t*2 (+1)
    if (PROJ) {
        float s[4] = {0.f, 0.f, 0.f, 0.f};   // rows: i0:g, i0:g+8, i1:g, i1:g+8
        #pragma unroll
        for (int i = 0; i < 2; ++i)
            #pragma unroll
            for (int j = 0; j < 8; ++j) {
                int col = n0 + wn + j * 8 + t * 2;
                float w0 = __ldg(wout + col), w1 = __ldg(wout + col + 1);
                float b0 = BIAS ? __ldg(bias + col) : 0.f;
                float b1 = BIAS ? __ldg(bias + col + 1) : 0.f;
                float v0 = acc[i][j][0] + b0, v1 = acc[i][j][1] + b1;
                float v2 = acc[i][j][2] + b0, v3 = acc[i][j][3] + b1;
                if (SILU) {
                    v0 = v0 / (1.f + __expf(-v0)); v1 = v1 / (1.f + __expf(-v1));
                    v2 = v2 / (1.f + __expf(-v2)); v3 = v3 / (1.f + __expf(-v3));
                }
                s[i * 2 + 0] += v0 * w0 + v1 * w1;
                s[i * 2 + 1] += v2 * w0 + v3 * w1;
            }
        // reduce over t (4 lanes within group)
        #pragma unroll
        for (int q = 0; q < 4; ++q) {
            s[q] += __shfl_xor_sync(0xffffffffu, s[q], 1);
            s[q] += __shfl_xor_sync(0xffffffffu, s[q], 2);
        }
        if (t == 0) {
            #pragma unroll
            for (int i = 0; i < 2; ++i) {
                int r0 = m0 + wm + i * 16 + g;
                if (r0 < M)
                    asm volatile("red.global.add.f32 [%0], %1;" :: "l"(Y + r0), "f"(s[i*2]) : "memory");
                if (r0 + 8 < M)
                    asm volatile("red.global.add.f32 [%0], %1;" :: "l"(Y + r0 + 8), "f"(s[i*2+1]) : "memory");
            }
        }
    } else {
        #pragma unroll
        for (int i = 0; i < 2; ++i) {
            int r0 = m0 + wm + i * 16 + g;
            #pragma unroll
            for (int j = 0; j < 8; ++j) {
                int col = n0 + wn + j * 8 + t * 2;
                float b0 = BIAS ? __ldg(bias + col) : 0.f;
                float b1 = BIAS ? __ldg(bias + col + 1) : 0.f;
                float v0 = acc[i][j][0] + b0, v1 = acc[i][j][1] + b1;
                float v2 = acc[i][j][2] + b0, v3 = acc[i][j][3] + b1;
                if (SILU) {
                    v0 = v0 / (1.f + __expf(-v0)); v1 = v1 / (1.f + __expf(-v1));
                    v2 = v2 / (1.f + __expf(-v2)); v3 = v3 / (1.f + __expf(-v3));
                }
                if (r0 < M)
                    *reinterpret_cast<float2*>(Y + (size_t)r0 * D_DIM + col) = make_float2(v0, v1);
                if (r0 + 8 < M)
                    *reinterpret_cast<float2*>(Y + (size_t)(r0 + 8) * D_DIM + col) = make_float2(v2, v3);
            }
        }
    }
}

// ---------------------------------------------------------------------------
// Launch
// Inputs: 0:x[E,128] 1:rbf[E,6] 2:i[E] 3:W_rbf[128,6] 4:W_up[256,128]
//         5:Ws[3,256,256] 6:bs[3,256] 7:W_out[1,256] (8:num_nodes)
// ---------------------------------------------------------------------------
extern "C" void kernel_launch(void* const* d_in, const int* in_sizes, int n_in,
                              void* d_out, int out_size) {
    const float* x     = (const float*)d_in[0];
    const float* rbf   = (const float*)d_in[1];
    const int*   idx   = (const int*)  d_in[2];
    const float* W_rbf = (const float*)d_in[3];
    const float* W_up  = (const float*)d_in[4];
    const float* Ws    = (const float*)d_in[5];
    const float* bs    = (const float*)d_in[6];
    const float* W_out = (const float*)d_in[7];
    float* out = (float*)d_out;

    const int E = in_sizes[2];
    const int M = out_size;

    float *agg, *y0, *y1;
    __nv_bfloat16 *whi, *wlo;
    cudaGetSymbolAddress((void**)&agg, g_agg);
    cudaGetSymbolAddress((void**)&y0,  g_y0);
    cudaGetSymbolAddress((void**)&y1,  g_y1);
    cudaGetSymbolAddress((void**)&whi, g_whi);
    cudaGetSymbolAddress((void**)&wlo, g_wlo);

    // weight split + zero agg/out
    prep_w<<<224, 256>>>(W_up, Ws, whi, wlo);
    zero_kernel<<<1024, 256>>>((float4*)agg, M * H_DIM / 4);
    zero_kernel<<<128, 256>>>((float4*)out, M / 4);

    // edge scatter
    edge_kernel<<<1184, 256>>>(x, rbf, idx, W_rbf, agg, E);

    const int tiles = (M + 127) / 128;
    dim3 grid(tiles, 2);
    const __nv_bfloat16* whi_l = whi + 256 * 128;
    const __nv_bfloat16* wlo_l = wlo + 256 * 128;

    // up-projection: y0 = agg @ W_up^T
    gemm_mma<128, false, false, false><<<grid, 256>>>(agg, whi, wlo, nullptr, nullptr, y0, M);
    // layer 0/1: ping-pong
    gemm_mma<256, true, true, false><<<grid, 256>>>(y0, whi_l + 0*65536, wlo_l + 0*65536, bs + 0*D_DIM, nullptr, y1, M);
    gemm_mma<256, true, true, false><<<grid, 256>>>(y1, whi_l + 1*65536, wlo_l + 1*65536, bs + 1*D_DIM, nullptr, y0, M);
    // layer 2 + fused projection into out
    gemm_mma<256, true, true, true ><<<grid, 256>>>(y0, whi_l + 2*65536, wlo_l + 2*65536, bs + 2*D_DIM, W_out, out, M);
}